// round 17
// baseline (speedup 1.0000x reference)
#include <cuda_runtime.h>
#include <cuda_fp16.h>
#include <mma.h>
using namespace nvcuda;

#define DIM 128
#define MAX_NODES 65536

__device__ __half g_Qh[MAX_NODES * 256];
__device__ __half g_nfh[MAX_NODES * DIM];
__device__ int g_idx64;

typedef wmma::fragment<wmma::matrix_a, 16, 16, 16, __half, wmma::row_major> FragA;
typedef wmma::fragment<wmma::matrix_b, 16, 16, 16, __half, wmma::row_major> FragB;
typedef wmma::fragment<wmma::accumulator, 16, 16, 16, float> FragC;

__device__ __forceinline__ unsigned su32(const void* p) {
    return (unsigned)__cvta_generic_to_shared(p);
}

// ---------------------------------------------------------------------------
// Precompute (r16, known-good): Q[node][half*128+c] = residual @ W1{b,c},
// single-pass fp16, b1 folded into dst half, Q fp16, nf fp16 copy, fused detect.
// ---------------------------------------------------------------------------
#define PRE_SMEM (128 * 136 * 2 + 128 * 132 * 4)

__global__ __launch_bounds__(512, 2)
void precompute_kernel(const float* __restrict__ nf, const float* __restrict__ centroid,
                       const float* __restrict__ W1, const float* __restrict__ b1,
                       const unsigned* __restrict__ eiw, int n_nodes, int npg) {
    extern __shared__ char sm[];
    __half* sW    = (__half*)sm;             // [128 k][136 n]
    char* sU      = sm + 128 * 136 * 2;      // union region
    __half* sA    = (__half*)sU;             // [128 node][136 k]
    float* sStage = (float*)sU;              // [128 node][132 c] (alias)

    const int t = threadIdx.x;
    const int half = blockIdx.x & 1;
    const int base = (blockIdx.x >> 1) * 128;

    if (blockIdx.x == 0) {
        __shared__ int s_any;
        if (t == 0) s_any = 0;
        __syncthreads();
        int found = 0;
        for (int i = t; i < 4096; i += 512)
            if (eiw[2 * i + 1] != 0u) found = 1;
        if (found) atomicOr(&s_any, 1);
        __syncthreads();
        if (t == 0) g_idx64 = (s_any == 0) ? 1 : 0;
    }

    const float* Wsrc = W1 + (1 + half) * DIM * DIM;
    for (int i = t; i < 128 * 128; i += 512) {
        int k = i >> 7, n = i & 127;
        sW[k * 136 + n] = __float2half_rn(Wsrc[i]);
    }
    __syncthreads();

    if (base + 128 > n_nodes) {
        for (int node = base; node < n_nodes; node++) {
            const float* row = nf + (size_t)node * DIM;
            const float* cen = centroid + (size_t)(node / npg) * DIM;
            if (half == 0)
                for (int d = t; d < DIM; d += 512)
                    g_nfh[(size_t)node * DIM + d] = __float2half_rn(row[d]);
            for (int c = t; c < 128; c += 512) {
                const float* wc = Wsrc + c;
                float acc = 0.f;
                for (int k = 0; k < DIM; k++) acc += (row[k] - cen[k]) * wc[k * DIM];
                if (half == 0) acc += b1[c];
                g_Qh[(size_t)node * 256 + half * 128 + c] = __float2half_rn(acc);
            }
        }
        return;
    }

    for (int i = t; i < 128 * 32; i += 512) {
        int node = i >> 5, c4 = i & 31;
        float4 v = ((const float4*)nf)[(size_t)(base + node) * 32 + c4];
        float4 c = ((const float4*)centroid)[(size_t)((base + node) / npg) * 32 + c4];
        if (half == 0) {
            __half2 n0 = __floats2half2_rn(v.x, v.y);
            __half2 n1 = __floats2half2_rn(v.z, v.w);
            ((uint2*)(g_nfh + (size_t)(base + node) * DIM))[c4] =
                make_uint2(*(unsigned*)&n0, *(unsigned*)&n1);
        }
        __half2 r0 = __floats2half2_rn(v.x - c.x, v.y - c.y);
        __half2 r1 = __floats2half2_rn(v.z - c.z, v.w - c.w);
        ((uint2*)(sA + node * 136))[c4] =
            make_uint2(*(unsigned*)&r0, *(unsigned*)&r1);
    }
    __syncthreads();

    const int w = t >> 5;
    const int np = w & 3;
    const int mp = w >> 2;
    {
        const __half* Ah = sA + (mp * 32) * 136;
        FragC acc[2][2];
#pragma unroll
        for (int mi = 0; mi < 2; mi++)
#pragma unroll
            for (int n = 0; n < 2; n++) wmma::fill_fragment(acc[mi][n], 0.f);
#pragma unroll
        for (int k = 0; k < 8; k++) {
            FragB b0, b1f;
            const __half* bp = sW + (k * 16) * 136 + np * 32;
            wmma::load_matrix_sync(b0, bp, 136);
            wmma::load_matrix_sync(b1f, bp + 16, 136);
#pragma unroll
            for (int mi = 0; mi < 2; mi++) {
                FragA af;
                wmma::load_matrix_sync(af, Ah + (mi * 16) * 136 + k * 16, 136);
                wmma::mma_sync(acc[mi][0], af, b0, acc[mi][0]);
                wmma::mma_sync(acc[mi][1], af, b1f, acc[mi][1]);
            }
        }
        __syncthreads();
#pragma unroll
        for (int mi = 0; mi < 2; mi++)
#pragma unroll
            for (int n = 0; n < 2; n++)
                wmma::store_matrix_sync(
                    sStage + (mp * 32 + mi * 16) * 132 + np * 32 + n * 16,
                    acc[mi][n], 132, wmma::mem_row_major);
    }
    __syncthreads();

    for (int i = t; i < 128 * 64; i += 512) {
        int node = i >> 6, cp = i & 63;
        float v0 = sStage[node * 132 + 2 * cp];
        float v1 = sStage[node * 132 + 2 * cp + 1];
        if (half == 0) { v0 += b1[2 * cp]; v1 += b1[2 * cp + 1]; }
        __half2 hv = __floats2half2_rn(v0, v1);
        *(__half2*)(g_Qh + (size_t)(base + node) * 256 + half * 128 + 2 * cp) = hv;
    }
}

// ---------------------------------------------------------------------------
// Edge kernel: raw mma.m16n8k16, register-resident epilogue, NO sOut.
// 512 thr = 4 groups x 4 warps; group = 64-edge tile (A 64x136 fp16 private).
// Warp (mq, nh): rows mq*32..+32, cols nh*64..+64 (2 chunks of 32 = 4 n8).
// Per chunk: k-loop mma -> fuse relu(Q+C).W2 into per-row partials from regs.
// Cross-nh partials combined via sPart (128 floats/group). 2 group barriers.
// ---------------------------------------------------------------------------
#define A_G (64 * 136 * 2)                            // 17408 B per group
#define EDGE_SMEM (128 * 136 * 2 + 4 * A_G + 512 /*W2f*/ + 4 * 512 /*sIdx*/ \
                   + 4 * 512 /*sPart*/ + 256)

#define BARG(gid) asm volatile("bar.sync %0, %1;" :: "r"((gid) + 1), "n"(128) : "memory")

__device__ __forceinline__ void ldm_x4(unsigned a[4], unsigned addr) {
    asm volatile("ldmatrix.sync.aligned.m8n8.x4.shared.b16 {%0,%1,%2,%3}, [%4];"
                 : "=r"(a[0]), "=r"(a[1]), "=r"(a[2]), "=r"(a[3]) : "r"(addr));
}
__device__ __forceinline__ void ldm_x2t(unsigned b[2], unsigned addr) {
    asm volatile("ldmatrix.sync.aligned.m8n8.x2.trans.shared.b16 {%0,%1}, [%2];"
                 : "=r"(b[0]), "=r"(b[1]) : "r"(addr));
}
__device__ __forceinline__ void mma16816(float c[4], const unsigned a[4],
                                         const unsigned b[2]) {
    asm volatile("mma.sync.aligned.m16n8k16.row.col.f32.f16.f16.f32 "
                 "{%0,%1,%2,%3}, {%4,%5,%6,%7}, {%8,%9}, {%0,%1,%2,%3};"
                 : "+f"(c[0]), "+f"(c[1]), "+f"(c[2]), "+f"(c[3])
                 : "r"(a[0]), "r"(a[1]), "r"(a[2]), "r"(a[3]),
                   "r"(b[0]), "r"(b[1]));
}

__global__ __launch_bounds__(512, 2)
void edge_kernel(const void* __restrict__ ei,
                 const float* __restrict__ W1,
                 const float* __restrict__ W2, const float* __restrict__ b2,
                 float* __restrict__ out, int E) {
    extern __shared__ char sm[];
    __half* sW = (__half*)sm;                            // [128 k][136 n]
    char* sAall = sm + 128 * 136 * 2;
    float* sW2f = (float*)(sAall + 4 * A_G);             // 128 floats
    int* sIdxAll = (int*)(sW2f + 128);                   // 4 groups x 128
    float* sPartAll = (float*)(sIdxAll + 4 * 128);       // 4 groups x 128

    const int t = threadIdx.x;
    for (int i = t; i < DIM * DIM; i += 512) {
        int k = i >> 7, n = i & 127;
        sW[k * 136 + n] = __float2half_rn(W1[i]);        // W1a block [k][n]
    }
    if (t < DIM) sW2f[t] = W2[t];
    __syncthreads();

    const int w = t >> 5;
    const int lane = t & 31;
    const int g4 = w >> 2;          // group 0..3
    const int wg = w & 3;           // warp in group
    const int mq = wg & 1;          // row half (32 rows)
    const int nh = wg >> 1;         // col half (64 cols)
    const int gid = lane >> 2;      // mma group id (row in 8-row half)
    const int tig = lane & 3;

    __half* sA = (__half*)(sAall + g4 * A_G);   // [64 e][136 k]
    int* sIdx = sIdxAll + g4 * 128;             // [0:64) src, [64:128) dst
    float* sPart = sPartAll + g4 * 128;         // [nh*64 + row]

    const unsigned sA_u = su32(sA);
    const unsigned sW_u = su32(sW);
    const float bias2 = b2[0];

    const int mode64 = g_idx64;
    const long long* ei64 = (const long long*)ei;
    const int* ei32 = (const int*)ei;

    // per-lane invariant ldmatrix address parts
    const unsigned aRowPart = (unsigned)(lane & 15) * 272 + ((lane >> 4) ? 16u : 0u);
    const unsigned bRowPart = (unsigned)(lane & 15) * 272;

    const int ngroups = gridDim.x * 4;
    const int niter = (E + 63) >> 6;
    for (int it = blockIdx.x * 4 + g4; it < niter; it += ngroups) {
        const int gbase = it * 64;

        // ---- gather: this warp loads+writes 16 edges (rows wg*16..+16) ----
        int idxg = 0;
        {
            int eidL = gbase + wg * 16 + (lane & 15);
            if (eidL < E) {
                size_t off = (lane < 16) ? (size_t)eidL : (size_t)E + eidL;
                idxg = mode64 ? (int)ei64[off] : ei32[off];
            }
            if (lane < 16) sIdx[wg * 16 + lane] = idxg;
            else           sIdx[64 + wg * 16 + (lane & 15)] = idxg;
        }
#pragma unroll
        for (int i = 0; i < 16; i++) {
            int sv = __shfl_sync(0xffffffffu, idxg, i);
            int dv = __shfl_sync(0xffffffffu, idxg, 16 + i);
            uint2 av = __ldg((const uint2*)(g_nfh + (size_t)dv * DIM) + lane);
            uint2 bv = __ldg((const uint2*)(g_nfh + (size_t)sv * DIM) + lane);
            __half2 d0 = __habs2(__hsub2(*(__half2*)&av.x, *(__half2*)&bv.x));
            __half2 d1 = __habs2(__hsub2(*(__half2*)&av.y, *(__half2*)&bv.y));
            ((uint2*)(sA + (wg * 16 + i) * 136))[lane] =
                make_uint2(*(unsigned*)&d0, *(unsigned*)&d1);
        }
        BARG(g4);

        // ---- MMA + fused epilogue: warp covers rows mq*32..+32, cols nh*64..+64
        float s[4];   // [mi*2 + rowhalf] per-row partial sums
#pragma unroll
        for (int i = 0; i < 4; i++) s[i] = 0.f;

#pragma unroll
        for (int ch = 0; ch < 2; ch++) {
            float c[2][4][4];
#pragma unroll
            for (int mi = 0; mi < 2; mi++)
#pragma unroll
                for (int j = 0; j < 4; j++)
#pragma unroll
                    for (int q = 0; q < 4; q++) c[mi][j][q] = 0.f;

            const int c0base = nh * 64 + ch * 32;   // absolute col of chunk
#pragma unroll
            for (int k = 0; k < 8; k++) {
                unsigned bfr[4][2];
#pragma unroll
                for (int j = 0; j < 4; j++)
                    ldm_x2t(bfr[j], sW_u + (unsigned)(k * 16) * 272 + bRowPart
                                     + (unsigned)(c0base + j * 8) * 2);
#pragma unroll
                for (int mi = 0; mi < 2; mi++) {
                    unsigned afr[4];
                    ldm_x4(afr, sA_u + (unsigned)((mq * 32 + mi * 16) * 272)
                                 + aRowPart + (unsigned)(k * 32));
#pragma unroll
                    for (int j = 0; j < 4; j++)
                        mma16816(c[mi][j], afr, bfr[j]);
                }
            }

            // fused epilogue for this chunk, straight from C registers
#pragma unroll
            for (int mi = 0; mi < 2; mi++) {
                int r0 = mq * 32 + mi * 16 + gid;
                int dv0 = sIdx[64 + r0], sv0 = sIdx[r0];
                int dv8 = sIdx[64 + r0 + 8], sv8 = sIdx[r0 + 8];
                const __half* qd0p = g_Qh + (size_t)dv0 * 256;
                const __half* qs0p = g_Qh + (size_t)sv0 * 256 + 128;
                const __half* qd8p = g_Qh + (size_t)dv8 * 256;
                const __half* qs8p = g_Qh + (size_t)sv8 * 256 + 128;
#pragma unroll
                for (int j = 0; j < 4; j++) {
                    int cc = c0base + j * 8 + 2 * tig;
                    float2 w2p = *(const float2*)(sW2f + cc);
                    float2 qd0 = __half22float2(*(const __half2*)(qd0p + cc));
                    float2 qs0 = __half22float2(*(const __half2*)(qs0p + cc));
                    float2 qd8 = __half22float2(*(const __half2*)(qd8p + cc));
                    float2 qs8 = __half22float2(*(const __half2*)(qs8p + cc));
                    s[mi * 2 + 0] += fmaxf(c[mi][j][0] + qd0.x + qs0.x, 0.f) * w2p.x
                                   + fmaxf(c[mi][j][1] + qd0.y + qs0.y, 0.f) * w2p.y;
                    s[mi * 2 + 1] += fmaxf(c[mi][j][2] + qd8.x + qs8.x, 0.f) * w2p.x
                                   + fmaxf(c[mi][j][3] + qd8.y + qs8.y, 0.f) * w2p.y;
                }
            }
        }

        // quad-reduce (cols live on the 4 tig lanes) and publish partials
#pragma unroll
        for (int i = 0; i < 4; i++) {
            s[i] += __shfl_xor_sync(0xffffffffu, s[i], 1);
            s[i] += __shfl_xor_sync(0xffffffffu, s[i], 2);
        }
        if (tig == 0) {
#pragma unroll
            for (int mi = 0; mi < 2; mi++) {
                sPart[nh * 64 + mq * 32 + mi * 16 + gid] = s[mi * 2 + 0];
                sPart[nh * 64 + mq * 32 + mi * 16 + 8 + gid] = s[mi * 2 + 1];
            }
        }
        BARG(g4);

        // combine n-halves and store (warps 0-1 of group cover 64 rows)
        if (wg < 2) {
            int row = wg * 32 + lane;
            float tot = sPart[row] + sPart[64 + row];
            int eid = gbase + row;
            if (eid < E) out[eid] = tot + bias2;
        }
        // no third barrier needed: next gather's A-writes only race with
        // A-reads that finished before BARG above; sPart next written after
        // the next gather barrier, by which time the combine reads are done.
    }
}

// ---------------------------------------------------------------------------
extern "C" void kernel_launch(void* const* d_in, const int* in_sizes, int n_in,
                              void* d_out, int out_size) {
    const float *nf = 0, *centroid = 0, *W1 = 0, *b1 = 0, *W2 = 0, *b2 = 0;
    const void* ei = 0;
    int nf_elems = 0, cen_elems = 0;
    int last_size1 = -1;

    for (int i = 0; i < n_in; i++) {
        int s = in_sizes[i];
        if (s == 1) { last_size1 = i; continue; }
        if (s == 128) {
            if (!b1) b1 = (const float*)d_in[i];
            else     W2 = (const float*)d_in[i];
            continue;
        }
        if (s == 2048) { centroid = (const float*)d_in[i]; cen_elems = s; continue; }
        if (s == 49152) { W1 = (const float*)d_in[i]; continue; }
        if (s == 2 * out_size) { ei = d_in[i]; continue; }
        if (s > nf_elems) { nf = (const float*)d_in[i]; nf_elems = s; }
    }
    if (last_size1 >= 0) b2 = (const float*)d_in[last_size1];

    const int E = out_size;
    const int n_nodes = nf_elems / DIM;
    const int bs = cen_elems / DIM;
    const int npg = n_nodes / (bs > 0 ? bs : 1);

    cudaFuncSetAttribute(precompute_kernel,
                         cudaFuncAttributeMaxDynamicSharedMemorySize, PRE_SMEM);
    precompute_kernel<<<((n_nodes + 127) / 128) * 2, 512, PRE_SMEM>>>(
        nf, centroid, W1, b1, (const unsigned*)ei, n_nodes, npg);

    int sms = 148;
    cudaDeviceGetAttribute(&sms, cudaDevAttrMultiProcessorCount, 0);

    cudaFuncSetAttribute(edge_kernel,
                         cudaFuncAttributeMaxDynamicSharedMemorySize, EDGE_SMEM);
    edge_kernel<<<sms * 2, 512, EDGE_SMEM>>>(ei, W1, W2, b2, (float*)d_out, E);
}